// round 10
// baseline (speedup 1.0000x reference)
#include <cuda_runtime.h>
#include <cuda_fp16.h>
#include <cstdint>
#include <cstddef>

// ============================================================================
// Problem constants. Harness dtypes: x/SCB/bias = float32 (fp16 values upcast
// losslessly), CB = int32, output = float32.
// ============================================================================
static constexpr int D_IN   = 4096;
static constexpr int D_OUT  = 11008;
static constexpr int M_TOT  = 8192;                 // 4 * 2048
static constexpr int BM     = 128;
static constexpr int BN     = 128;
static constexpr int BK     = 64;                   // halves per stage (128 B rows)
static constexpr int KITERS = D_IN / BK;            // 64
static constexpr int STAGES = 3;
static constexpr int TILES_M = M_TOT / BM;          // 64
static constexpr int TILES_N = D_OUT / BN;          // 86
static constexpr int A_BYTES = BM * BK * 2;         // 16 KB
static constexpr int STAGE_BYTES = (BM + BN) * BK * 2;  // 32 KB
static constexpr int SMEM_BYTES  = STAGES * STAGE_BYTES + 1024; // 97 KB

// Device-global scratch (allocation-free): fp16 copies of x and dequantized W
__device__ __align__(16) __half g_X[(size_t)M_TOT * D_IN];   // 64 MB
__device__ __align__(16) __half g_W[(size_t)D_OUT * D_IN];   // 90 MB

// ============================================================================
// Helpers
// ============================================================================
__device__ __forceinline__ uint32_t smem_u32(const void* p) {
    uint32_t a;
    asm("{ .reg .u64 t; cvta.to.shared.u64 t, %1; cvt.u32.u64 %0, t; }"
        : "=r"(a) : "l"(p));
    return a;
}

__device__ __forceinline__ void cp_async16(uint32_t dst, const void* src) {
    asm volatile("cp.async.cg.shared.global [%0], [%1], 16;"
                 :: "r"(dst), "l"(src) : "memory");
}
#define CP_COMMIT() asm volatile("cp.async.commit_group;" ::: "memory")
#define CP_WAIT0()  asm volatile("cp.async.wait_group 0;" ::: "memory")
#define CP_WAIT1()  asm volatile("cp.async.wait_group 1;" ::: "memory")

// ============================================================================
// Kernel 1 (merged prep): x fp32->fp16 AND dequant CB int32 -> W fp16.
// Dequant matches reference fp16 chain: s = fp16(SCB)/fp16(127); W = fp16(CB)*s.
// ============================================================================
static constexpr size_t NX_VEC = (size_t)M_TOT * D_IN / 8;     // 4,194,304
static constexpr size_t NW_VEC = (size_t)D_OUT * D_IN / 8;     // 5,636,096
static constexpr int PREP_BLOCKS = (int)((NX_VEC + NW_VEC) / 256);  // 38400

__global__ __launch_bounds__(256) void prep_kernel(const float* __restrict__ xf,
                                                   const int* __restrict__ CB,
                                                   const float* __restrict__ SCB) {
    size_t i = (size_t)blockIdx.x * 256 + threadIdx.x;
    if (i < NX_VEC) {
        const float4* p = (const float4*)xf + i * 2;
        float4 a = p[0], b = p[1];
        union { uint4 v; __half2 h[4]; } u;
        u.h[0] = __floats2half2_rn(a.x, a.y);
        u.h[1] = __floats2half2_rn(a.z, a.w);
        u.h[2] = __floats2half2_rn(b.x, b.y);
        u.h[3] = __floats2half2_rn(b.z, b.w);
        ((uint4*)g_X)[i] = u.v;
    } else {
        size_t j = i - NX_VEC;
        int n = (int)(j >> 9);                           // (j*8)/4096
        __half s = __hdiv(__float2half_rn(SCB[n]), __float2half(127.0f));
        const int4* p = (const int4*)CB + j * 2;
        int4 a = p[0], b = p[1];
        union { uint4 v; __half2 h[4]; } u;
        u.h[0] = __halves2half2(__hmul(__int2half_rn(a.x), s), __hmul(__int2half_rn(a.y), s));
        u.h[1] = __halves2half2(__hmul(__int2half_rn(a.z), s), __hmul(__int2half_rn(a.w), s));
        u.h[2] = __halves2half2(__hmul(__int2half_rn(b.x), s), __hmul(__int2half_rn(b.y), s));
        u.h[3] = __halves2half2(__hmul(__int2half_rn(b.z), s), __hmul(__int2half_rn(b.w), s));
        ((uint4*)g_W)[j] = u.v;
    }
}

// ============================================================================
// Kernel 2: mma.sync fp16 GEMM. CTA 128x128x64, 4 warps (2x2), warp tile 64x64,
// 3-stage cp.async pipeline, 2 CTAs/SM, register-double-buffered fragments.
// SINGLE barrier per k-iter at ks2:
//   ld_frags(kb=96)  [last read of recycled stage]
//   cp.async.wait_group 0   [retires iter k-1's group: stage k+1 landed;
//                            only 1 group outstanding -> effectively free]
//   __syncthreads           [orders everyone's last-read AND wait before...]
//   load_stage(k+2)         [...overwrite of recycled stage]
//   commit
// ks3 then reads stage k+1 safely (all warps' waits precede the barrier).
// SW128 swizzle: sw(row, cb) = row*128 + (cb ^ ((row&7)<<4)); per-ks address
// trick: kb ∈ {0,32,64,96} -> addr(ks) = (stage_base + tile_const) ^ kb.
// ============================================================================
__device__ __forceinline__ void load_stage(int m0, int n0, int k,
                                           uint32_t sbA, int tid) {
    uint32_t base = sbA + (uint32_t)(k % STAGES) * STAGE_BYTES;
    int k0 = k * BK;
    int r = tid >> 3;            // 0..15
    int c = tid & 7;             // 16B chunk in row
    uint32_t cbx = (uint32_t)(c * 16) ^ (uint32_t)((r & 7) << 4);
#pragma unroll
    for (int i = 0; i < 8; ++i) {                       // A rows r, r+16, ...
        int rr = r + i * 16;
        cp_async16(base + (uint32_t)rr * 128 + cbx,
                   g_X + (size_t)(m0 + rr) * D_IN + k0 + c * 8);
    }
    uint32_t bbase = base + A_BYTES;
#pragma unroll
    for (int i = 0; i < 8; ++i) {                       // B rows r, r+16, ...
        int rr = r + i * 16;
        cp_async16(bbase + (uint32_t)rr * 128 + cbx,
                   g_W + (size_t)(n0 + rr) * D_IN + k0 + c * 8);
    }
}

__device__ __forceinline__ void ld_frags(uint32_t sa, uint32_t kb,
                                         const uint32_t ta[4], const uint32_t tb[4],
                                         uint32_t RA[4][4], uint32_t RB[4][4]) {
#pragma unroll
    for (int mt = 0; mt < 4; ++mt) {
        uint32_t addr = (sa + ta[mt]) ^ kb;
        asm volatile("ldmatrix.sync.aligned.m8n8.x4.shared.b16 {%0,%1,%2,%3}, [%4];"
            : "=r"(RA[mt][0]), "=r"(RA[mt][1]), "=r"(RA[mt][2]), "=r"(RA[mt][3])
            : "r"(addr));
    }
#pragma unroll
    for (int p = 0; p < 4; ++p) {
        uint32_t addr = (sa + tb[p]) ^ kb;
        asm volatile("ldmatrix.sync.aligned.m8n8.x4.shared.b16 {%0,%1,%2,%3}, [%4];"
            : "=r"(RB[p][0]), "=r"(RB[p][1]), "=r"(RB[p][2]), "=r"(RB[p][3])
            : "r"(addr));
    }
}

__global__ __launch_bounds__(128, 2)
void gemm_kernel(const float* __restrict__ biasf,
                 float* __restrict__ out) {
    extern __shared__ char smem[];
    uint32_t sbA = (smem_u32(smem) + 1023u) & ~1023u;   // 1K-aligned stage base
    int tid  = threadIdx.x;
    int lane = tid & 31;
    int wid  = tid >> 5;         // 0..3
    int warp_m = wid >> 1;       // 0..1 (64 rows each)
    int warp_n = wid & 1;        // 0..1 (64 cols each)

    // Grouped rasterization: 8 m-tiles per supergroup, n fastest (B stays in L2)
    const int per = 8 * TILES_N;
    int g  = blockIdx.x / per;
    int r  = blockIdx.x % per;
    int mi = g * 8 + (r & 7);
    int ni = r >> 3;
    int m0 = mi * BM;
    int n0 = ni * BN;

    // Tile constants: toff = row*128 + (colbase ^ ((row&7)<<4))
    uint32_t ta[4], tb[4];
    {
        uint32_t acb = (uint32_t)((lane >> 4) * 16);
        uint32_t bcb = (uint32_t)(((lane >> 3) & 1) * 16);
#pragma unroll
        for (int mt = 0; mt < 4; ++mt) {
            int row = warp_m * 64 + mt * 16 + ((lane >> 3) & 1) * 8 + (lane & 7);
            ta[mt] = (uint32_t)row * 128 + (acb ^ (uint32_t)((row & 7) << 4));
        }
#pragma unroll
        for (int p = 0; p < 4; ++p) {
            int row = warp_n * 64 + p * 16 + ((lane >> 4) * 8) + (lane & 7);
            tb[p] = (uint32_t)A_BYTES + (uint32_t)row * 128 +
                    (bcb ^ (uint32_t)((row & 7) << 4));
        }
    }

    float acc[4][8][4];
#pragma unroll
    for (int i = 0; i < 4; ++i)
#pragma unroll
        for (int j = 0; j < 8; ++j)
#pragma unroll
            for (int q = 0; q < 4; ++q) acc[i][j][q] = 0.0f;

    uint32_t RA[2][4][4], RB[2][4][4];

    // Prologue: fill stages 0,1; wait stage 0 (leave stage 1 in flight);
    // load frags(0, ks=0).
    load_stage(m0, n0, 0, sbA, tid); CP_COMMIT();
    load_stage(m0, n0, 1, sbA, tid); CP_COMMIT();
    CP_WAIT1();
    __syncthreads();
    ld_frags(sbA, 0, ta, tb, RA[0], RB[0]);

#pragma unroll 1
    for (int k = 0; k < KITERS; ++k) {
        uint32_t sa = sbA + (uint32_t)(k % STAGES) * STAGE_BYTES;
#pragma unroll
        for (int ks = 0; ks < 4; ++ks) {
            const int cur = ks & 1;
            const int nxt = cur ^ 1;

            if (ks < 2) {
                // frags(k, ks+1) — covered by this ks's 32 MMAs
                ld_frags(sa, (uint32_t)((ks + 1) * 32), ta, tb, RA[nxt], RB[nxt]);
            } else if (ks == 2) {
                // Last read (kb=96) of the recycled stage.
                ld_frags(sa, 96u, ta, tb, RA[nxt], RB[nxt]);
                CP_WAIT0();        // retire iter k-1's group (stage k+1 landed)
                __syncthreads();   // anti-dep + visibility in one barrier
                if (k + 2 < KITERS) load_stage(m0, n0, k + 2, sbA, tid);
                CP_COMMIT();       // unconditional: uniform group accounting
            } else {               // ks == 3
                if (k + 1 < KITERS) {
                    uint32_t sa2 = sbA + (uint32_t)((k + 1) % STAGES) * STAGE_BYTES;
                    ld_frags(sa2, 0, ta, tb, RA[nxt], RB[nxt]);
                }
            }

#pragma unroll
            for (int mt = 0; mt < 4; ++mt)
#pragma unroll
                for (int nt = 0; nt < 8; ++nt) {
                    uint32_t b0 = RB[cur][nt >> 1][(nt & 1) * 2];
                    uint32_t b1 = RB[cur][nt >> 1][(nt & 1) * 2 + 1];
                    asm volatile(
                        "mma.sync.aligned.m16n8k16.row.col.f32.f16.f16.f32 "
                        "{%0,%1,%2,%3}, {%4,%5,%6,%7}, {%8,%9}, {%0,%1,%2,%3};"
                        : "+f"(acc[mt][nt][0]), "+f"(acc[mt][nt][1]),
                          "+f"(acc[mt][nt][2]), "+f"(acc[mt][nt][3])
                        : "r"(RA[cur][mt][0]), "r"(RA[cur][mt][1]),
                          "r"(RA[cur][mt][2]), "r"(RA[cur][mt][3]),
                          "r"(b0), "r"(b1));
                }
        }
    }

    // Epilogue: fp16(acc_f32) + fp16(bias), then upcast to fp32 output
    int t2 = (lane & 3) * 2;
    int gg = lane >> 2;
#pragma unroll
    for (int nt = 0; nt < 8; ++nt) {
        int col = n0 + warp_n * 64 + nt * 8 + t2;
        float2 bf = *(const float2*)(biasf + col);
        __half blo = __float2half_rn(bf.x);
        __half bhi = __float2half_rn(bf.y);
#pragma unroll
        for (int mt = 0; mt < 4; ++mt) {
            int row0 = m0 + warp_m * 64 + mt * 16 + gg;
            float2 v0 = make_float2(
                __half2float(__hadd(__float2half_rn(acc[mt][nt][0]), blo)),
                __half2float(__hadd(__float2half_rn(acc[mt][nt][1]), bhi)));
            *(float2*)(out + (size_t)row0 * D_OUT + col) = v0;
            float2 v1 = make_float2(
                __half2float(__hadd(__float2half_rn(acc[mt][nt][2]), blo)),
                __half2float(__hadd(__float2half_rn(acc[mt][nt][3]), bhi)));
            *(float2*)(out + (size_t)(row0 + 8) * D_OUT + col) = v1;
        }
    }
}

// ============================================================================
// Launch
// ============================================================================
extern "C" void kernel_launch(void* const* d_in, const int* in_sizes, int n_in,
                              void* d_out, int out_size) {
    const float* x    = (const float*)d_in[0];
    const int*   CB   = (const int*)d_in[1];
    const float* SCB  = (const float*)d_in[2];
    const float* bias = (const float*)d_in[3];
    float* out = (float*)d_out;

    // 1) Merged prep: x->fp16 and W dequant
    prep_kernel<<<PREP_BLOCKS, 256>>>(x, CB, SCB);

    // 2) Tensor-core GEMM (legacy mma.sync — tcgen05 blocked by the harness's
    //    compute_103 virtual-arch compile), 2 CTAs/SM, 64x64 warp tiles,
    //    fragment double-buffering, single barrier per k-iteration.
    cudaFuncSetAttribute(gemm_kernel, cudaFuncAttributeMaxDynamicSharedMemorySize,
                         SMEM_BYTES);
    gemm_kernel<<<TILES_M * TILES_N, 128, SMEM_BYTES>>>(bias, out);
}

// round 11
// speedup vs baseline: 1.0186x; 1.0186x over previous
#include <cuda_runtime.h>
#include <cuda_fp16.h>
#include <cstdint>
#include <cstddef>

// ============================================================================
// Problem constants. Harness dtypes: x/SCB/bias = float32 (fp16 values upcast
// losslessly), CB = int32, output = float32.
// ============================================================================
static constexpr int D_IN   = 4096;
static constexpr int D_OUT  = 11008;
static constexpr int M_TOT  = 8192;                 // 4 * 2048
static constexpr int BM     = 128;
static constexpr int BN     = 128;
static constexpr int BK     = 64;                   // halves per stage (128 B rows)
static constexpr int KITERS = D_IN / BK;            // 64
static constexpr int STAGES = 3;
static constexpr int TILES_M = M_TOT / BM;          // 64
static constexpr int TILES_N = D_OUT / BN;          // 86
static constexpr int A_BYTES = BM * BK * 2;         // 16 KB
static constexpr int STAGE_BYTES = (BM + BN) * BK * 2;  // 32 KB
static constexpr int SMEM_BYTES  = STAGES * STAGE_BYTES + 1024; // 97 KB

// Device-global scratch (allocation-free): fp16 copies of x and dequantized W
__device__ __align__(16) __half g_X[(size_t)M_TOT * D_IN];   // 64 MB
__device__ __align__(16) __half g_W[(size_t)D_OUT * D_IN];   // 90 MB

// ============================================================================
// Helpers
// ============================================================================
__device__ __forceinline__ uint32_t smem_u32(const void* p) {
    uint32_t a;
    asm("{ .reg .u64 t; cvta.to.shared.u64 t, %1; cvt.u32.u64 %0, t; }"
        : "=r"(a) : "l"(p));
    return a;
}

__device__ __forceinline__ void cp_async16(uint32_t dst, const void* src) {
    asm volatile("cp.async.cg.shared.global [%0], [%1], 16;"
                 :: "r"(dst), "l"(src) : "memory");
}
#define CP_COMMIT() asm volatile("cp.async.commit_group;" ::: "memory")
#define CP_WAIT1()  asm volatile("cp.async.wait_group 1;" ::: "memory")

// Named split barriers. CTA = 128 threads; each thread ARRIVEs once and SYNCs
// once per phase -> release count 256.
#define BAR_A_SYNC()   asm volatile("bar.sync 1, 256;" ::: "memory")
#define BAR_A_ARRIVE() asm volatile("bar.arrive 1, 256;" ::: "memory")
#define BAR_V_SYNC()   asm volatile("bar.sync 2, 256;" ::: "memory")
#define BAR_V_ARRIVE() asm volatile("bar.arrive 2, 256;" ::: "memory")

// ============================================================================
// Kernel 1 (merged prep): x fp32->fp16 AND dequant CB int32 -> W fp16.
// Dequant matches reference fp16 chain: s = fp16(SCB)/fp16(127); W = fp16(CB)*s.
// ============================================================================
static constexpr size_t NX_VEC = (size_t)M_TOT * D_IN / 8;     // 4,194,304
static constexpr size_t NW_VEC = (size_t)D_OUT * D_IN / 8;     // 5,636,096
static constexpr int PREP_BLOCKS = (int)((NX_VEC + NW_VEC) / 256);  // 38400

__global__ __launch_bounds__(256) void prep_kernel(const float* __restrict__ xf,
                                                   const int* __restrict__ CB,
                                                   const float* __restrict__ SCB) {
    size_t i = (size_t)blockIdx.x * 256 + threadIdx.x;
    if (i < NX_VEC) {
        const float4* p = (const float4*)xf + i * 2;
        float4 a = p[0], b = p[1];
        union { uint4 v; __half2 h[4]; } u;
        u.h[0] = __floats2half2_rn(a.x, a.y);
        u.h[1] = __floats2half2_rn(a.z, a.w);
        u.h[2] = __floats2half2_rn(b.x, b.y);
        u.h[3] = __floats2half2_rn(b.z, b.w);
        ((uint4*)g_X)[i] = u.v;
    } else {
        size_t j = i - NX_VEC;
        int n = (int)(j >> 9);                           // (j*8)/4096
        __half s = __hdiv(__float2half_rn(SCB[n]), __float2half(127.0f));
        const int4* p = (const int4*)CB + j * 2;
        int4 a = p[0], b = p[1];
        union { uint4 v; __half2 h[4]; } u;
        u.h[0] = __halves2half2(__hmul(__int2half_rn(a.x), s), __hmul(__int2half_rn(a.y), s));
        u.h[1] = __halves2half2(__hmul(__int2half_rn(a.z), s), __hmul(__int2half_rn(a.w), s));
        u.h[2] = __halves2half2(__hmul(__int2half_rn(b.x), s), __hmul(__int2half_rn(b.y), s));
        u.h[3] = __halves2half2(__hmul(__int2half_rn(b.z), s), __hmul(__int2half_rn(b.w), s));
        ((uint4*)g_W)[j] = u.v;
    }
}

// ============================================================================
// Kernel 2: mma.sync fp16 GEMM. CTA 128x128x64, 4 warps (2x2), warp tile 64x64,
// 3-stage cp.async pipeline, 2 CTAs/SM, register-double-buffered fragments,
// R9 two-named-barrier protocol, and (new) the 16-LDGSTS stage prefetch
// INTERLEAVED into the ks2 MMA stream (1 cp.async per 2 MMAs) so the in-order
// issue stream never parks the tensor pipe behind an LSU burst.
//
// SW128 swizzle: sw(row, cb) = row*128 + (cb ^ ((row&7)<<4)); per-ks address
// trick: kb ∈ {0,32,64,96} -> addr(ks) = (stage_base + tile_const) ^ kb.
// ============================================================================
__device__ __forceinline__ void ld_frags(uint32_t sa, uint32_t kb,
                                         const uint32_t ta[4], const uint32_t tb[4],
                                         uint32_t RA[4][4], uint32_t RB[4][4]) {
#pragma unroll
    for (int mt = 0; mt < 4; ++mt) {
        uint32_t addr = (sa + ta[mt]) ^ kb;
        asm volatile("ldmatrix.sync.aligned.m8n8.x4.shared.b16 {%0,%1,%2,%3}, [%4];"
            : "=r"(RA[mt][0]), "=r"(RA[mt][1]), "=r"(RA[mt][2]), "=r"(RA[mt][3])
            : "r"(addr));
    }
#pragma unroll
    for (int p = 0; p < 4; ++p) {
        uint32_t addr = (sa + tb[p]) ^ kb;
        asm volatile("ldmatrix.sync.aligned.m8n8.x4.shared.b16 {%0,%1,%2,%3}, [%4];"
            : "=r"(RB[p][0]), "=r"(RB[p][1]), "=r"(RB[p][2]), "=r"(RB[p][3])
            : "r"(addr));
    }
}

#define MMA_ONE(accp, RAf, b0, b1)                                          \
    asm volatile(                                                           \
        "mma.sync.aligned.m16n8k16.row.col.f32.f16.f16.f32 "                \
        "{%0,%1,%2,%3}, {%4,%5,%6,%7}, {%8,%9}, {%0,%1,%2,%3};"             \
        : "+f"((accp)[0]), "+f"((accp)[1]), "+f"((accp)[2]), "+f"((accp)[3])\
        : "r"((RAf)[0]), "r"((RAf)[1]), "r"((RAf)[2]), "r"((RAf)[3]),       \
          "r"(b0), "r"(b1))

__device__ __forceinline__ void mma_all(float acc[4][8][4],
                                        const uint32_t RA[4][4],
                                        const uint32_t RB[4][4]) {
#pragma unroll
    for (int mt = 0; mt < 4; ++mt)
#pragma unroll
        for (int nt = 0; nt < 8; ++nt)
            MMA_ONE(acc[mt][nt], RA[mt],
                    RB[nt >> 1][(nt & 1) * 2], RB[nt >> 1][(nt & 1) * 2 + 1]);
}

// ks2 variant: 32 MMAs with 16 cp.async interleaved (one per 2 MMAs).
__device__ __forceinline__ void mma_all_ld(float acc[4][8][4],
                                           const uint32_t RA[4][4],
                                           const uint32_t RB[4][4],
                                           bool doload,
                                           uint32_t smA, uint32_t smB,
                                           const __half* pA, const __half* pB) {
#pragma unroll
    for (int i = 0; i < 32; ++i) {
        int mt = i >> 3, nt = i & 7;
        MMA_ONE(acc[mt][nt], RA[mt],
                RB[nt >> 1][(nt & 1) * 2], RB[nt >> 1][(nt & 1) * 2 + 1]);
        if (!(i & 1) && doload) {
            int j = i >> 1;                         // 0..15
            if (j < 8) cp_async16(smA + (uint32_t)j * 2048, pA + (size_t)j * 16 * D_IN);
            else       cp_async16(smB + (uint32_t)(j - 8) * 2048,
                                  pB + (size_t)(j - 8) * 16 * D_IN);
        }
    }
}

__global__ __launch_bounds__(128, 2)
void gemm_kernel(const float* __restrict__ biasf,
                 float* __restrict__ out) {
    extern __shared__ char smem[];
    uint32_t sbA = (smem_u32(smem) + 1023u) & ~1023u;   // 1K-aligned stage base
    int tid  = threadIdx.x;
    int lane = tid & 31;
    int wid  = tid >> 5;         // 0..3
    int warp_m = wid >> 1;       // 0..1 (64 rows each)
    int warp_n = wid & 1;        // 0..1 (64 cols each)

    // Grouped rasterization: 8 m-tiles per supergroup, n fastest (B stays in L2)
    const int per = 8 * TILES_N;
    int g  = blockIdx.x / per;
    int r0 = blockIdx.x % per;
    int mi = g * 8 + (r0 & 7);
    int ni = r0 >> 3;
    int m0 = mi * BM;
    int n0 = ni * BN;

    // Per-thread gmem/smem constants for stage loading
    int lr = tid >> 3;           // 0..15
    int lc = tid & 7;            // 16B chunk
    uint32_t cbx = (uint32_t)(lc * 16) ^ (uint32_t)((lr & 7) << 4);
    const __half* pAg = g_X + (size_t)(m0 + lr) * D_IN + lc * 8;
    const __half* pBg = g_W + (size_t)(n0 + lr) * D_IN + lc * 8;
    uint32_t smO = (uint32_t)lr * 128 + cbx;   // smem offset within stage (A part)

    // Tile constants: toff = row*128 + (colbase ^ ((row&7)<<4))
    uint32_t ta[4], tb[4];
    {
        uint32_t acb = (uint32_t)((lane >> 4) * 16);
        uint32_t bcb = (uint32_t)(((lane >> 3) & 1) * 16);
#pragma unroll
        for (int mt = 0; mt < 4; ++mt) {
            int row = warp_m * 64 + mt * 16 + ((lane >> 3) & 1) * 8 + (lane & 7);
            ta[mt] = (uint32_t)row * 128 + (acb ^ (uint32_t)((row & 7) << 4));
        }
#pragma unroll
        for (int p = 0; p < 4; ++p) {
            int row = warp_n * 64 + p * 16 + ((lane >> 4) * 8) + (lane & 7);
            tb[p] = (uint32_t)A_BYTES + (uint32_t)row * 128 +
                    (bcb ^ (uint32_t)((row & 7) << 4));
        }
    }

    float acc[4][8][4];
#pragma unroll
    for (int i = 0; i < 4; ++i)
#pragma unroll
        for (int j = 0; j < 8; ++j)
#pragma unroll
            for (int q = 0; q < 4; ++q) acc[i][j][q] = 0.0f;

    uint32_t RA[2][4][4], RB[2][4][4];

    // Prologue: fill stages 0,1 (burst form is fine here — nothing to overlap)
#pragma unroll
    for (int s = 0; s < 2; ++s) {
        uint32_t base = sbA + (uint32_t)s * STAGE_BYTES;
#pragma unroll
        for (int j = 0; j < 8; ++j) {
            cp_async16(base + smO + (uint32_t)j * 2048,
                       pAg + (size_t)j * 16 * D_IN + s * BK);
            cp_async16(base + A_BYTES + smO + (uint32_t)j * 2048,
                       pBg + (size_t)j * 16 * D_IN + s * BK);
        }
        CP_COMMIT();
    }
    CP_WAIT1();
    __syncthreads();
    ld_frags(sbA, 0, ta, tb, RA[0], RB[0]);
    BAR_A_ARRIVE();                                    // prime anti-dep phase 0

#pragma unroll 1
    for (int k = 0; k < KITERS; ++k) {
        uint32_t sa = sbA + (uint32_t)(k % STAGES) * STAGE_BYTES;

        // seg0: consume buf0, load frags(k, kb=32) into buf1
        ld_frags(sa, 32u, ta, tb, RA[1], RB[1]);
        mma_all(acc, RA[0], RB[0]);

        // seg1: consume buf1, load frags(k, kb=64) into buf0
        ld_frags(sa, 64u, ta, tb, RA[0], RB[0]);
        mma_all(acc, RA[1], RB[1]);

        // seg2: consume buf0; last read (kb=96) of the recycled stage into buf1;
        // then anti-dep barrier and the INTERLEAVED stage-(k+2) prefetch.
        ld_frags(sa, 96u, ta, tb, RA[1], RB[1]);
        BAR_A_SYNC();              // all warps done reading the recycled stage
        {
            bool doload = (k + 2 < KITERS);
            uint32_t b2 = sbA + (uint32_t)((k + 2) % STAGES) * STAGE_BYTES;
            int k2 = (k + 2) * BK;
            mma_all_ld(acc, RA[0], RB[0], doload,
                       b2 + smO, b2 + A_BYTES + smO, pAg + k2, pBg + k2);
        }
        CP_COMMIT();               // unconditional: uniform group accounting
        CP_WAIT1();                // (k+1)-stage group has landed for this warp
        BAR_V_ARRIVE();            // publish visibility
        BAR_A_ARRIVE();            // done reading current stage (next recycle)

        // seg3: consume buf1; load frags(k+1, kb=0) from next stage into buf0
        if (k + 1 < KITERS) {
            BAR_V_SYNC();          // everyone's (k+1)-stage loads visible
            uint32_t sa2 = sbA + (uint32_t)((k + 1) % STAGES) * STAGE_BYTES;
            ld_frags(sa2, 0, ta, tb, RA[0], RB[0]);
        }
        mma_all(acc, RA[1], RB[1]);
    }

    // Epilogue: fp16(acc_f32) + fp16(bias), then upcast to fp32 output
    int t2 = (lane & 3) * 2;
    int gg = lane >> 2;
#pragma unroll
    for (int nt = 0; nt < 8; ++nt) {
        int col = n0 + warp_n * 64 + nt * 8 + t2;
        float2 bf = *(const float2*)(biasf + col);
        __half blo = __float2half_rn(bf.x);
        __half bhi = __float2half_rn(bf.y);
#pragma unroll
        for (int mt = 0; mt < 4; ++mt) {
            int row0 = m0 + warp_m * 64 + mt * 16 + gg;
            float2 v0 = make_float2(
                __half2float(__hadd(__float2half_rn(acc[mt][nt][0]), blo)),
                __half2float(__hadd(__float2half_rn(acc[mt][nt][1]), bhi)));
            *(float2*)(out + (size_t)row0 * D_OUT + col) = v0;
            float2 v1 = make_float2(
                __half2float(__hadd(__float2half_rn(acc[mt][nt][2]), blo)),
                __half2float(__hadd(__float2half_rn(acc[mt][nt][3]), bhi)));
            *(float2*)(out + (size_t)(row0 + 8) * D_OUT + col) = v1;
        }
    }
}

// ============================================================================
// Launch
// ============================================================================
extern "C" void kernel_launch(void* const* d_in, const int* in_sizes, int n_in,
                              void* d_out, int out_size) {
    const float* x    = (const float*)d_in[0];
    const int*   CB   = (const int*)d_in[1];
    const float* SCB  = (const float*)d_in[2];
    const float* bias = (const float*)d_in[3];
    float* out = (float*)d_out;

    // 1) Merged prep: x->fp16 and W dequant
    prep_kernel<<<PREP_BLOCKS, 256>>>(x, CB, SCB);

    // 2) Tensor-core GEMM (legacy mma.sync — tcgen05 blocked by the harness's
    //    compute_103 virtual-arch compile), 2 CTAs/SM, 64x64 warp tiles,
    //    fragment double-buffering, split barriers, interleaved prefetch.
    cudaFuncSetAttribute(gemm_kernel, cudaFuncAttributeMaxDynamicSharedMemorySize,
                         SMEM_BYTES);
    gemm_kernel<<<TILES_M * TILES_N, 128, SMEM_BYTES>>>(bias, out);
}